// round 3
// baseline (speedup 1.0000x reference)
#include <cuda_runtime.h>
#include <cstdint>

#define THREADS 512
#define ETILE   128
#define SA      68      // padded stride for 64-wide tiles (bank-conflict-free fragments)
#define SW2     196     // padded stride for W_mlp (192-wide)
#define LN_EPS  1e-5f

// shared-memory float offsets
#define OFF_EDGE 0                    // 128*68 = 8704 floats (aliased as "pre" after GEMM1)
#define OFF_E    8704                 // e tile
#define OFF_HEAD 17408
#define OFF_TAIL 26112
#define OFF_W1   34816                // 64*68
#define OFF_W2   39168                // 64*196
#define OFF_WAL  51712                // 192
#define OFF_BI   51904                // 64
#define OFF_BM   51968                // 64
#define OFF_BA   52032                // 1
#define SMEM_FLOATS 52036
#define SMEM_BYTES  (SMEM_FLOATS * 4)

// edges dtype flag: 1 if the edges buffer is genuinely int64, 0 if int32.
// (JAX with default x64-disabled silently makes "int64" arrays int32.)
__device__ int g_edges_is_i64;

__global__ void probe_edges_dtype(const long long* __restrict__ e64) {
    if (threadIdx.x == 0 && blockIdx.x == 0) {
        int ok = 1;
        #pragma unroll 8
        for (int i = 0; i < 64; ++i) {
            long long v = e64[i];
            if (v < 0 || v >= (1LL << 31)) ok = 0;   // int32 data misread as i64 -> huge
        }
        g_edges_is_i64 = ok;
    }
}

// round fp32 -> tf32 (rna) so HW truncation inside mma is exact (avoids biased error)
__device__ __forceinline__ uint32_t tf32r(float x) {
    uint32_t u;
    asm("cvt.rna.tf32.f32 %0, %1;" : "=r"(u) : "f"(x));
    return u;
}
__device__ __forceinline__ float tf32f(float x) { return __uint_as_float(tf32r(x)); }

__device__ __forceinline__ void mma_tf32(float c[4], const uint32_t a[4], const uint32_t b[2]) {
    asm volatile(
        "mma.sync.aligned.m16n8k8.row.col.f32.tf32.tf32.f32 "
        "{%0,%1,%2,%3}, {%4,%5,%6,%7}, {%8,%9}, {%0,%1,%2,%3};\n"
        : "+f"(c[0]), "+f"(c[1]), "+f"(c[2]), "+f"(c[3])
        : "r"(a[0]), "r"(a[1]), "r"(a[2]), "r"(a[3]), "r"(b[0]), "r"(b[1]));
}

__global__ void __launch_bounds__(THREADS, 1)
edge_update_kernel(const float* __restrict__ node_fts,
                   const float* __restrict__ edge_fts,
                   const void* __restrict__ edges_raw,
                   const float* __restrict__ W_init,
                   const float* __restrict__ b_init,
                   const float* __restrict__ W_mlp,
                   const float* __restrict__ b_mlp,
                   const float* __restrict__ W_alpha,
                   const float* __restrict__ b_alpha,
                   float* __restrict__ out,
                   int n_edges)
{
    extern __shared__ float sm[];
    const int tid  = threadIdx.x;
    const int base = blockIdx.x * ETILE;
    const int rem  = min(ETILE, n_edges - base);
    const int is64 = g_edges_is_i64;
    const long long* __restrict__ e64 = (const long long*)edges_raw;
    const int*       __restrict__ e32 = (const int*)edges_raw;

    // ---------------- phase 1: stage tiles + weights (tf32-rounded) ----------------
    {
        const int rr  = tid >> 4;          // 32 rows per pass
        const int seg = (tid & 15) * 4;    // 16 threads * float4 per 64-float row
        #pragma unroll
        for (int it = 0; it < 4; ++it) {
            int r = rr + it * 32;
            float4 v = make_float4(0.f, 0.f, 0.f, 0.f);
            float4 h = v, t = v;
            if (r < rem) {
                size_t e = (size_t)(base + r);
                v = *(const float4*)(edge_fts + e * 64 + seg);
                int hidx, tidx;
                if (is64) {
                    hidx = (int)e64[e];
                    tidx = (int)e64[(size_t)n_edges + e];
                } else {
                    hidx = e32[e];
                    tidx = e32[(size_t)n_edges + e];
                }
                h = *(const float4*)(node_fts + (size_t)hidx * 64 + seg);
                t = *(const float4*)(node_fts + (size_t)tidx * 64 + seg);
            }
            float* pe = sm + OFF_EDGE + r * SA + seg;
            pe[0] = tf32f(v.x); pe[1] = tf32f(v.y); pe[2] = tf32f(v.z); pe[3] = tf32f(v.w);
            float* ph = sm + OFF_HEAD + r * SA + seg;
            ph[0] = tf32f(h.x); ph[1] = tf32f(h.y); ph[2] = tf32f(h.z); ph[3] = tf32f(h.w);
            float* pt = sm + OFF_TAIL + r * SA + seg;
            pt[0] = tf32f(t.x); pt[1] = tf32f(t.y); pt[2] = tf32f(t.z); pt[3] = tf32f(t.w);
        }
        // W_init: 64x64, stored [n][k]
        for (int i = tid; i < 64 * 16; i += THREADS) {
            int rw = i >> 4, sg = (i & 15) * 4;
            float4 v = *(const float4*)(W_init + rw * 64 + sg);
            float* p = sm + OFF_W1 + rw * SA + sg;
            p[0] = tf32f(v.x); p[1] = tf32f(v.y); p[2] = tf32f(v.z); p[3] = tf32f(v.w);
        }
        // W_mlp: 64x192, stored [n][k]
        for (int i = tid; i < 64 * 48; i += THREADS) {
            int rw = i / 48, sg = (i % 48) * 4;
            float4 v = *(const float4*)(W_mlp + rw * 192 + sg);
            float* p = sm + OFF_W2 + rw * SW2 + sg;
            p[0] = tf32f(v.x); p[1] = tf32f(v.y); p[2] = tf32f(v.z); p[3] = tf32f(v.w);
        }
        if (tid < 192) sm[OFF_WAL + tid] = W_alpha[tid];
        if (tid < 64)  sm[OFF_BI + tid] = b_init[tid];
        else if (tid < 128) sm[OFF_BM + tid - 64] = b_mlp[tid - 64];
        else if (tid == 128) sm[OFF_BA] = b_alpha[0];
    }
    __syncthreads();

    const int warp = tid >> 5;
    const int lane = tid & 31;
    const int g    = lane >> 2;
    const int t4   = lane & 3;
    const int wm   = warp >> 1;        // 8 M-slices of 16 rows
    const int wn   = warp & 1;         // 2 N-slices of 32 cols
    const int row0 = wm * 16 + g;
    const int row1 = row0 + 8;
    const int ncol = wn * 32;

    float acc[4][4];

    // ---------------- GEMM1: e = edge @ W_init^T ----------------
    #pragma unroll
    for (int i = 0; i < 4; i++)
        #pragma unroll
        for (int j = 0; j < 4; j++) acc[i][j] = 0.f;

    {
        const float* A1 = sm + OFF_EDGE;
        const float* B1 = sm + OFF_W1;
        #pragma unroll
        for (int ks = 0; ks < 8; ++ks) {
            const int k0 = ks * 8;
            uint32_t a[4];
            a[0] = __float_as_uint(A1[row0 * SA + k0 + t4]);
            a[1] = __float_as_uint(A1[row1 * SA + k0 + t4]);
            a[2] = __float_as_uint(A1[row0 * SA + k0 + t4 + 4]);
            a[3] = __float_as_uint(A1[row1 * SA + k0 + t4 + 4]);
            #pragma unroll
            for (int nt = 0; nt < 4; ++nt) {
                const int n0 = ncol + nt * 8;
                uint32_t b[2];
                b[0] = __float_as_uint(B1[(n0 + g) * SA + k0 + t4]);
                b[1] = __float_as_uint(B1[(n0 + g) * SA + k0 + t4 + 4]);
                mma_tf32(acc[nt], a, b);
            }
        }
    }
    // write e (+b_init), tf32-rounded so GEMM2 consumes exact tf32
    #pragma unroll
    for (int nt = 0; nt < 4; ++nt) {
        const int c0 = ncol + nt * 8 + 2 * t4;
        const float b0 = sm[OFF_BI + c0], b1 = sm[OFF_BI + c0 + 1];
        *(float2*)(sm + OFF_E + row0 * SA + c0) =
            make_float2(tf32f(acc[nt][0] + b0), tf32f(acc[nt][1] + b1));
        *(float2*)(sm + OFF_E + row1 * SA + c0) =
            make_float2(tf32f(acc[nt][2] + b0), tf32f(acc[nt][3] + b1));
    }
    __syncthreads();

    // ---------------- GEMM2: pre = [e|head|tail] @ W_mlp^T ----------------
    #pragma unroll
    for (int i = 0; i < 4; i++)
        #pragma unroll
        for (int j = 0; j < 4; j++) acc[i][j] = 0.f;

    {
        const float* B2 = sm + OFF_W2;
        #pragma unroll
        for (int ks = 0; ks < 24; ++ks) {
            const float* Ab = sm + ((ks < 8) ? OFF_E : (ks < 16) ? OFF_HEAD : OFF_TAIL);
            const int k0 = (ks & 7) * 8;
            const int kw = ks * 8;
            uint32_t a[4];
            a[0] = __float_as_uint(Ab[row0 * SA + k0 + t4]);
            a[1] = __float_as_uint(Ab[row1 * SA + k0 + t4]);
            a[2] = __float_as_uint(Ab[row0 * SA + k0 + t4 + 4]);
            a[3] = __float_as_uint(Ab[row1 * SA + k0 + t4 + 4]);
            #pragma unroll
            for (int nt = 0; nt < 4; ++nt) {
                const int n0 = ncol + nt * 8;
                uint32_t b[2];
                b[0] = __float_as_uint(B2[(n0 + g) * SW2 + kw + t4]);
                b[1] = __float_as_uint(B2[(n0 + g) * SW2 + kw + t4 + 4]);
                mma_tf32(acc[nt], a, b);
            }
        }
    }
    // write pre (alias of edge tile buffer; edge tile is dead after GEMM1)
    #pragma unroll
    for (int nt = 0; nt < 4; ++nt) {
        const int c0 = ncol + nt * 8 + 2 * t4;
        *(float2*)(sm + OFF_EDGE + row0 * SA + c0) = make_float2(acc[nt][0], acc[nt][1]);
        *(float2*)(sm + OFF_EDGE + row1 * SA + c0) = make_float2(acc[nt][2], acc[nt][3]);
    }
    __syncthreads();

    // ---------------- epilogue: alpha, tanh, LN, LN, store ----------------
    {
        const float balpha = sm[OFF_BA];
        const int c0 = lane, c1 = lane + 32;
        for (int rr = 0; rr < 8; ++rr) {
            const int r = warp * 8 + rr;
            const float* pre = sm + OFF_EDGE + r * SA;
            const float* er  = sm + OFF_E + r * SA;
            float p0 = tanhf(pre[c0] + sm[OFF_BM + c0]);
            float p1 = tanhf(pre[c1] + sm[OFF_BM + c1]);
            // alpha partial: combined[k] * W_alpha[k]
            float ap = 0.f;
            #pragma unroll
            for (int j = 0; j < 6; ++j) {
                const int k = lane + 32 * j;
                float cv = (k < 64) ? er[k]
                         : (k < 128) ? sm[OFF_HEAD + r * SA + k - 64]
                                     : sm[OFF_TAIL + r * SA + k - 128];
                ap += cv * sm[OFF_WAL + k];
            }
            float s1 = p0 + p1;
            float s2 = p0 * p0 + p1 * p1;
            #pragma unroll
            for (int off = 16; off; off >>= 1) {
                s1 += __shfl_xor_sync(0xffffffffu, s1, off);
                s2 += __shfl_xor_sync(0xffffffffu, s2, off);
                ap += __shfl_xor_sync(0xffffffffu, ap, off);
            }
            const float alpha = 1.f / (1.f + expf(-(ap + balpha)));
            const float mean  = s1 * (1.f / 64.f);
            const float var   = s2 * (1.f / 64.f) - mean * mean;
            const float rstd  = rsqrtf(var + LN_EPS) * alpha;
            float y0 = er[c0] + (p0 - mean) * rstd;
            float y1 = er[c1] + (p1 - mean) * rstd;
            float u1 = y0 + y1, u2 = y0 * y0 + y1 * y1;
            #pragma unroll
            for (int off = 16; off; off >>= 1) {
                u1 += __shfl_xor_sync(0xffffffffu, u1, off);
                u2 += __shfl_xor_sync(0xffffffffu, u2, off);
            }
            const float m2  = u1 * (1.f / 64.f);
            const float v2  = u2 * (1.f / 64.f) - m2 * m2;
            const float rs2 = rsqrtf(v2 + LN_EPS);
            if (r < rem) {
                const size_t o = (size_t)(base + r) * 64;
                out[o + c0] = (y0 - m2) * rs2;
                out[o + c1] = (y1 - m2) * rs2;
            }
        }
    }
}

extern "C" void kernel_launch(void* const* d_in, const int* in_sizes, int n_in,
                              void* d_out, int out_size)
{
    const float* node_fts = (const float*)d_in[0];
    const float* edge_fts = (const float*)d_in[1];
    const void*  edges    = d_in[2];
    const float* W_init   = (const float*)d_in[3];
    const float* b_init   = (const float*)d_in[4];
    const float* W_mlp    = (const float*)d_in[5];
    const float* b_mlp    = (const float*)d_in[6];
    const float* W_alpha  = (const float*)d_in[7];
    const float* b_alpha  = (const float*)d_in[8];
    float*       out      = (float*)d_out;

    const int n_edges = in_sizes[1] / 64;      // edge_fts elements / EDGE_IN_FTS
    const int grid    = (n_edges + ETILE - 1) / ETILE;

    cudaFuncSetAttribute(edge_update_kernel,
                         cudaFuncAttributeMaxDynamicSharedMemorySize, SMEM_BYTES);
    probe_edges_dtype<<<1, 32>>>((const long long*)edges);
    edge_update_kernel<<<grid, THREADS, SMEM_BYTES>>>(
        node_fts, edge_fts, edges, W_init, b_init,
        W_mlp, b_mlp, W_alpha, b_alpha, out, n_edges);
}

// round 5
// speedup vs baseline: 1.3457x; 1.3457x over previous
#include <cuda_runtime.h>
#include <cstdint>

#define NT 512
#define LN_EPS 1e-5f

// ---- shared memory float offsets ----
#define F_W1   0              // W_init, 64 x stride 68
#define F_WB   4352           // Wbig (Wc|W2h|W2t ; alpha row ; zero pad), 72 x stride 196
#define F_BI   18464          // b_init [64]
#define F_BMX  18528          // folded bias [65] (pad to 68)
#define F_A    18596          // per-group buffers
#define GSZ    17408          // 4 buffers x 64 x 68 per group
// within group: EDGE +0, HEAD +4352, TAIL +8704, E +13056 (col 64 of E = alpha)
#define SM_FLOATS (F_A + 2 * GSZ)      // 53412
#define SMEM_BYTES (SM_FLOATS * 4)     // 213648

__device__ int g_edges_is_i64;

__global__ void probe_edges_dtype(const long long* __restrict__ e64) {
    if (threadIdx.x == 0) {
        int ok = 1;
        for (int i = 0; i < 64; ++i) {
            long long v = e64[i];
            if (v < 0 || v >= (1LL << 31)) ok = 0;
        }
        g_edges_is_i64 = ok;
    }
}

__device__ __forceinline__ uint32_t smem_u32(const void* p) {
    uint32_t a;
    asm("{ .reg .u64 t; cvta.to.shared.u64 t, %1; cvt.u32.u64 %0, t; }" : "=r"(a) : "l"(p));
    return a;
}
__device__ __forceinline__ float tf32f(float x) {
    uint32_t u; asm("cvt.rna.tf32.f32 %0, %1;" : "=r"(u) : "f"(x));
    return __uint_as_float(u);
}
__device__ __forceinline__ void cp16(uint32_t dst, const void* src) {
    asm volatile("cp.async.cg.shared.global [%0], [%1], 16;" :: "r"(dst), "l"(src));
}
__device__ __forceinline__ void cp_commit()  { asm volatile("cp.async.commit_group;" ::: "memory"); }
__device__ __forceinline__ void cp_waitall() { asm volatile("cp.async.wait_group 0;" ::: "memory"); }
__device__ __forceinline__ void barg(int id) {
    asm volatile("bar.sync %0, %1;" :: "r"(id), "r"(256) : "memory");
}
__device__ __forceinline__ void mma_tf32(float c[4], const uint32_t a[4], const uint32_t b[2]) {
    asm volatile(
        "mma.sync.aligned.m16n8k8.row.col.f32.tf32.tf32.f32 "
        "{%0,%1,%2,%3}, {%4,%5,%6,%7}, {%8,%9}, {%0,%1,%2,%3};\n"
        : "+f"(c[0]), "+f"(c[1]), "+f"(c[2]), "+f"(c[3])
        : "r"(a[0]), "r"(a[1]), "r"(a[2]), "r"(a[3]), "r"(b[0]), "r"(b[1]));
}

// stage EDGE + TAIL rows of a 64-row tile; 256 threads, 8 cp16 each
__device__ __forceinline__ void stage_ET(
    uint32_t su_e, uint32_t su_t, int tb, int rem, int n_edges, int is64,
    const float* __restrict__ edge_fts, const float* __restrict__ node_fts,
    const long long* __restrict__ e64, const int* __restrict__ e32, int ltid)
{
    const int r = ltid >> 2, q = ltid & 3;
    if (r < rem) {
        const float* se = edge_fts + (size_t)(tb + r) * 64 + q * 16;
        uint32_t de = su_e + (uint32_t)(r * 68 + q * 16) * 4u;
        #pragma unroll
        for (int i = 0; i < 4; ++i) cp16(de + i * 16, se + i * 4);
        size_t ep = (size_t)n_edges + (size_t)(tb + r);
        int idx = is64 ? (int)e64[ep] : e32[ep];
        const float* st = node_fts + (size_t)idx * 64 + q * 16;
        uint32_t dt = su_t + (uint32_t)(r * 68 + q * 16) * 4u;
        #pragma unroll
        for (int i = 0; i < 4; ++i) cp16(dt + i * 16, st + i * 4);
    }
}

// stage HEAD rows owned by this warp (rows wi*8 .. wi*8+7); 4 cp16 per lane
__device__ __forceinline__ void stage_H(
    uint32_t su_h, int tb, int rem, int is64,
    const float* __restrict__ node_fts,
    const long long* __restrict__ e64, const int* __restrict__ e32,
    int wi, int lane)
{
    const int r = wi * 8 + (lane >> 2), q = lane & 3;
    if (r < rem) {
        size_t ep = (size_t)(tb + r);
        int idx = is64 ? (int)e64[ep] : e32[ep];
        const float* sh = node_fts + (size_t)idx * 64 + q * 16;
        uint32_t dh = su_h + (uint32_t)(r * 68 + q * 16) * 4u;
        #pragma unroll
        for (int i = 0; i < 4; ++i) cp16(dh + i * 16, sh + i * 4);
    }
}

__global__ void __launch_bounds__(NT, 1)
edge_update_v5(const float* __restrict__ node_fts,
               const float* __restrict__ edge_fts,
               const void* __restrict__ edges_raw,
               const float* __restrict__ W_init,
               const float* __restrict__ b_init,
               const float* __restrict__ W_mlp,
               const float* __restrict__ b_mlp,
               const float* __restrict__ W_alpha,
               const float* __restrict__ b_alpha,
               float* __restrict__ out,
               int n_edges)
{
    extern __shared__ float sm[];
    const uint32_t su = smem_u32(sm);
    const int tid  = threadIdx.x;
    const int is64 = g_edges_is_i64;
    const long long* e64 = (const long long*)edges_raw;
    const int*       e32 = (const int*)edges_raw;

    // ---------------- one-time setup ----------------
    // W1 (rna-rounded), stride 68
    for (int i = tid; i < 64 * 64; i += NT)
        sm[F_W1 + (i >> 6) * 68 + (i & 63)] = tf32f(W_init[i]);
    // Wbig: rows 0-63 = [Wc | W2h | W2t]; row 64 = [wa_e@W1 | wa_h | wa_t]; rows 65-71 = 0
    for (int i = tid; i < 72 * 192; i += NT) {
        int n = i / 192, k = i - n * 192;
        float v = 0.f;
        if (n < 64) {
            if (k < 64) {
                float s = 0.f;
                #pragma unroll 8
                for (int j = 0; j < 64; ++j) s += W_mlp[n * 192 + j] * W_init[j * 64 + k];
                v = s;
            } else v = W_mlp[n * 192 + k];
        } else if (n == 64) {
            if (k < 64) {
                float s = 0.f;
                #pragma unroll 8
                for (int j = 0; j < 64; ++j) s += W_alpha[j] * W_init[j * 64 + k];
                v = s;
            } else v = W_alpha[k];
        }
        sm[F_WB + n * 196 + k] = tf32f(v);
    }
    if (tid < 64) sm[F_BI + tid] = b_init[tid];
    if (tid < 65) {
        float s = (tid < 64) ? b_mlp[tid] : b_alpha[0];
        const float* wr = (tid < 64) ? (W_mlp + tid * 192) : W_alpha;
        #pragma unroll 8
        for (int j = 0; j < 64; ++j) s += b_init[j] * wr[j];
        sm[F_BMX + tid] = s;
    }
    __syncthreads();

    // ---------------- group decomposition ----------------
    const int grp  = tid >> 8;            // 0 or 1
    const int ltid = tid & 255;
    const int wi   = ltid >> 5;           // warp-in-group 0..7
    const int lane = tid & 31;
    const int g_   = lane >> 2;
    const int t4   = lane & 3;
    const int bid  = grp + 1;             // named barrier id

    const int GB     = F_A + grp * GSZ;
    float* EDGE = sm + GB;
    float* HEAD = sm + GB + 4352;         // aliased as PRE after GEMM
    float* TAIL = sm + GB + 8704;
    float* EB   = sm + GB + 13056;        // e ; col 64 = alpha pre-act
    const uint32_t suE = su + (uint32_t)GB * 4u;
    const uint32_t suH = suE + 4352 * 4;
    const uint32_t suT = suE + 8704 * 4;

    const int T      = (n_edges + 63) >> 6;
    const int stride = gridDim.x * 2;
    const int t0     = blockIdx.x * 2 + grp;

    // prologue staging
    if (t0 < T) {
        int tb = t0 << 6, rem = min(64, n_edges - tb);
        stage_ET(suE, suT, tb, rem, n_edges, is64, edge_fts, node_fts, e64, e32, ltid);
        stage_H(suH, tb, rem, is64, node_fts, e64, e32, wi, lane);
    }
    cp_commit();

    for (int t = t0; t < T; t += stride) {
        const int tb  = t << 6;
        const int rem = min(64, n_edges - tb);
        const int tn  = t + stride;
        const int tbn = tn << 6;
        const int remn = (tn < T) ? min(64, n_edges - tbn) : 0;

        cp_waitall();
        barg(bid);

        // ---------------- GEMMs (independent) ----------------
        if (wi >= 6) {
            // e-GEMM: 32 rows x 64 cols, K=64 over EDGE @ W1^T
            const int rowb = (wi - 6) * 32;
            float acc[2][8][4];
            #pragma unroll
            for (int a = 0; a < 2; ++a)
                #pragma unroll
                for (int b = 0; b < 8; ++b)
                    #pragma unroll
                    for (int c = 0; c < 4; ++c) acc[a][b][c] = 0.f;
            #pragma unroll
            for (int ks = 0; ks < 8; ++ks) {
                const int k0 = ks * 8;
                uint32_t a[2][4];
                #pragma unroll
                for (int mt = 0; mt < 2; ++mt) {
                    const int r0 = rowb + mt * 16 + g_;
                    a[mt][0] = __float_as_uint(EDGE[r0 * 68 + k0 + t4]);
                    a[mt][1] = __float_as_uint(EDGE[(r0 + 8) * 68 + k0 + t4]);
                    a[mt][2] = __float_as_uint(EDGE[r0 * 68 + k0 + t4 + 4]);
                    a[mt][3] = __float_as_uint(EDGE[(r0 + 8) * 68 + k0 + t4 + 4]);
                }
                #pragma unroll
                for (int nt = 0; nt < 8; ++nt) {
                    uint32_t b[2];
                    b[0] = __float_as_uint(sm[F_W1 + (nt * 8 + g_) * 68 + k0 + t4]);
                    b[1] = __float_as_uint(sm[F_W1 + (nt * 8 + g_) * 68 + k0 + t4 + 4]);
                    mma_tf32(acc[0][nt], a[0], b);
                    mma_tf32(acc[1][nt], a[1], b);
                }
            }
            barg(bid);
            // write e (+b_init) to EB
            #pragma unroll
            for (int mt = 0; mt < 2; ++mt) {
                const int r0 = rowb + mt * 16 + g_;
                #pragma unroll
                for (int nt = 0; nt < 8; ++nt) {
                    const int c = nt * 8 + 2 * t4;
                    const float b0 = sm[F_BI + c], b1 = sm[F_BI + c + 1];
                    *(float2*)(EB + r0 * 68 + c) = make_float2(acc[mt][nt][0] + b0, acc[mt][nt][1] + b1);
                    *(float2*)(EB + (r0 + 8) * 68 + c) = make_float2(acc[mt][nt][2] + b0, acc[mt][nt][3] + b1);
                }
            }
        } else {
            // big-GEMM: 32 rows x 24 cols, K=192 over [EDGE|HEAD|TAIL] @ Wbig^T
            const int rowb = (wi / 3) * 32;
            const int n0   = (wi % 3) * 24;
            float acc[2][3][4];
            #pragma unroll
            for (int a = 0; a < 2; ++a)
                #pragma unroll
                for (int b = 0; b < 3; ++b)
                    #pragma unroll
                    for (int c = 0; c < 4; ++c) acc[a][b][c] = 0.f;
            #pragma unroll
            for (int ks = 0; ks < 24; ++ks) {
                const float* A = (ks < 8) ? EDGE : (ks < 16) ? HEAD : TAIL;
                const int k0 = (ks & 7) * 8;
                const int kw = ks * 8;
                uint32_t a[2][4];
                #pragma unroll
                for (int mt = 0; mt < 2; ++mt) {
                    const int r0 = rowb + mt * 16 + g_;
                    a[mt][0] = __float_as_uint(A[r0 * 68 + k0 + t4]);
                    a[mt][1] = __float_as_uint(A[(r0 + 8) * 68 + k0 + t4]);
                    a[mt][2] = __float_as_uint(A[r0 * 68 + k0 + t4 + 4]);
                    a[mt][3] = __float_as_uint(A[(r0 + 8) * 68 + k0 + t4 + 4]);
                }
                #pragma unroll
                for (int nt = 0; nt < 3; ++nt) {
                    uint32_t b[2];
                    b[0] = __float_as_uint(sm[F_WB + (n0 + nt * 8 + g_) * 196 + kw + t4]);
                    b[1] = __float_as_uint(sm[F_WB + (n0 + nt * 8 + g_) * 196 + kw + t4 + 4]);
                    mma_tf32(acc[0][nt], a[0], b);
                    mma_tf32(acc[1][nt], a[1], b);
                }
            }
            barg(bid);
            // write pre to HEAD (dead), alpha col 64 to EB
            #pragma unroll
            for (int mt = 0; mt < 2; ++mt) {
                const int r0 = rowb + mt * 16 + g_;
                #pragma unroll
                for (int nt = 0; nt < 3; ++nt) {
                    const int c = n0 + nt * 8 + 2 * t4;
                    if (c < 64) {
                        *(float2*)(HEAD + r0 * 68 + c) = make_float2(acc[mt][nt][0], acc[mt][nt][1]);
                        *(float2*)(HEAD + (r0 + 8) * 68 + c) = make_float2(acc[mt][nt][2], acc[mt][nt][3]);
                    } else if (c == 64) {
                        EB[r0 * 68 + 64] = acc[mt][nt][0];
                        EB[(r0 + 8) * 68 + 64] = acc[mt][nt][2];
                    }
                }
            }
        }

        // prefetch next EDGE+TAIL (both dead)
        if (tn < T)
            stage_ET(suE, suT, tbn, remn, n_edges, is64, edge_fts, node_fts, e64, e32, ltid);
        cp_commit();
        barg(bid);

        // ---------------- epilogue: warp wi owns rows wi*8..+7 ----------------
        float pr0[8], pr1[8], ee0[8], ee1[8], ap[8];
        #pragma unroll
        for (int j = 0; j < 8; ++j) {
            const int r = wi * 8 + j;
            pr0[j] = HEAD[r * 68 + lane];
            pr1[j] = HEAD[r * 68 + 32 + lane];
            ee0[j] = EB[r * 68 + lane];
            ee1[j] = EB[r * 68 + 32 + lane];
            ap[j]  = EB[r * 68 + 64];
        }
        // re-stage HEAD rows this warp just consumed
        if (tn < T)
            stage_H(suH, tbn, remn, is64, node_fts, e64, e32, wi, lane);
        cp_commit();

        const float bm0 = sm[F_BMX + lane], bm1 = sm[F_BMX + 32 + lane];
        const float ba  = sm[F_BMX + 64];
        #pragma unroll
        for (int j = 0; j < 8; ++j) {
            const int r = wi * 8 + j;
            float q0 = pr0[j] + bm0, q1 = pr1[j] + bm1;
            float x0 = __expf(-2.f * fabsf(q0));
            float x1 = __expf(-2.f * fabsf(q1));
            float p0 = copysignf((1.f - x0) / (1.f + x0), q0);
            float p1 = copysignf((1.f - x1) / (1.f + x1), q1);
            const float alpha = 1.f / (1.f + __expf(-(ap[j] + ba)));
            float s1 = p0 + p1, s2 = p0 * p0 + p1 * p1;
            #pragma unroll
            for (int off = 16; off; off >>= 1) {
                s1 += __shfl_xor_sync(0xffffffffu, s1, off);
                s2 += __shfl_xor_sync(0xffffffffu, s2, off);
            }
            const float mean = s1 * (1.f / 64.f);
            const float var  = s2 * (1.f / 64.f) - mean * mean;
            const float rstd = rsqrtf(var + LN_EPS) * alpha;
            float y0 = ee0[j] + (p0 - mean) * rstd;
            float y1 = ee1[j] + (p1 - mean) * rstd;
            float u1 = y0 + y1, u2 = y0 * y0 + y1 * y1;
            #pragma unroll
            for (int off = 16; off; off >>= 1) {
                u1 += __shfl_xor_sync(0xffffffffu, u1, off);
                u2 += __shfl_xor_sync(0xffffffffu, u2, off);
            }
            const float m2  = u1 * (1.f / 64.f);
            const float v2  = u2 * (1.f / 64.f) - m2 * m2;
            const float rs2 = rsqrtf(v2 + LN_EPS);
            if (r < rem) {
                float* op = out + (size_t)(tb + r) * 64;
                op[lane]      = (y0 - m2) * rs2;
                op[lane + 32] = (y1 - m2) * rs2;
            }
        }
    }
}

extern "C" void kernel_launch(void* const* d_in, const int* in_sizes, int n_in,
                              void* d_out, int out_size)
{
    const float* node_fts = (const float*)d_in[0];
    const float* edge_fts = (const float*)d_in[1];
    const void*  edges    = d_in[2];
    const float* W_init   = (const float*)d_in[3];
    const float* b_init   = (const float*)d_in[4];
    const float* W_mlp    = (const float*)d_in[5];
    const float* b_mlp    = (const float*)d_in[6];
    const float* W_alpha  = (const float*)d_in[7];
    const float* b_alpha  = (const float*)d_in[8];
    float*       out      = (float*)d_out;

    const int n_edges = in_sizes[1] / 64;
    const int T = (n_edges + 63) / 64;

    int nsm = 148;
    cudaDeviceGetAttribute(&nsm, cudaDevAttrMultiProcessorCount, 0);
    int grid = (T + 1) / 2 < nsm ? (T + 1) / 2 : nsm;

    cudaFuncSetAttribute(edge_update_v5,
                         cudaFuncAttributeMaxDynamicSharedMemorySize, SMEM_BYTES);
    probe_edges_dtype<<<1, 32>>>((const long long*)edges);
    edge_update_v5<<<grid, NT, SMEM_BYTES>>>(
        node_fts, edge_fts, edges, W_init, b_init,
        W_mlp, b_mlp, W_alpha, b_alpha, out, n_edges);
}

// round 6
// speedup vs baseline: 1.9023x; 1.4136x over previous
#include <cuda_runtime.h>
#include <cstdint>

#define NT 384
#define LN_EPS 1e-5f

// ---- smem float offsets ----
#define F_W1P 0                      // W_init frag-packed: 64 rows x stride 88
#define F_WBP 5632                   // Wbig frag-packed:  72 rows x stride 216
#define F_BMX 21184                  // folded bias [65]
#define F_E   21252                  // per-warp e buffers: 12 x (32 x 72)
#define EW    2304
#define SM_FLOATS (F_E + 12 * EW)    // 48900
#define SMEM_BYTES (SM_FLOATS * 4)   // 195600

__device__ int g_edges_is_i64;

__global__ void probe_edges_dtype(const long long* __restrict__ e64) {
    if (threadIdx.x == 0) {
        int ok = 1;
        for (int i = 0; i < 64; ++i) {
            long long v = e64[i];
            if (v < 0 || v >= (1LL << 31)) ok = 0;
        }
        g_edges_is_i64 = ok;
    }
}

__device__ __forceinline__ float tf32f(float x) {
    uint32_t u; asm("cvt.rna.tf32.f32 %0, %1;" : "=r"(u) : "f"(x));
    return __uint_as_float(u);
}
__device__ __forceinline__ void mma_tf32(float c[4], const uint32_t a[4], const uint32_t b[2]) {
    asm volatile(
        "mma.sync.aligned.m16n8k8.row.col.f32.tf32.tf32.f32 "
        "{%0,%1,%2,%3}, {%4,%5,%6,%7}, {%8,%9}, {%0,%1,%2,%3};\n"
        : "+f"(c[0]), "+f"(c[1]), "+f"(c[2]), "+f"(c[3])
        : "r"(a[0]), "r"(a[1]), "r"(a[2]), "r"(a[3]), "r"(b[0]), "r"(b[1]));
}
__device__ __forceinline__ uint32_t ldgu(const char* p) {
    return __float_as_uint(__ldg((const float*)p));
}

__global__ void __launch_bounds__(NT, 1)
edge_update_v6(const float* __restrict__ node_fts,
               const float* __restrict__ edge_fts,
               const void* __restrict__ edges_raw,
               const float* __restrict__ W_init,
               const float* __restrict__ b_init,
               const float* __restrict__ W_mlp,
               const float* __restrict__ b_mlp,
               const float* __restrict__ W_alpha,
               const float* __restrict__ b_alpha,
               float* __restrict__ out,
               int n_edges)
{
    extern __shared__ float sm[];
    const int tid  = threadIdx.x;
    const int wid  = tid >> 5;
    const int lane = tid & 31;
    const int g_   = lane >> 2;
    const int t4   = lane & 3;
    const int is64 = g_edges_is_i64;
    const long long* e64 = (const long long*)edges_raw;
    const int*       e32 = (const int*)edges_raw;

    // ---------------- one-time setup ----------------
    // W1 frag-packed: pair (k0+t, k0+t+4) adjacent
    for (int i = tid; i < 64 * 64; i += NT) {
        int n = i >> 6, k = i & 63, ks = k >> 3, t = k & 7;
        int pos = F_W1P + n * 88 + ((t < 4) ? (ks * 8 + t) * 2 : (ks * 8 + t - 4) * 2 + 1);
        sm[pos] = tf32f(W_init[i]);
    }
    // Wbig = rows 0-63 [Wc | W2h | W2t], row 64 alpha, rows 65-71 zero ; frag-packed
    for (int i = tid; i < 72 * 192; i += NT) {
        int n = i / 192, k = i - n * 192;
        float v = 0.f;
        if (n < 64) {
            if (k < 64) {
                float s = 0.f;
                #pragma unroll 8
                for (int j = 0; j < 64; ++j) s += W_mlp[n * 192 + j] * W_init[j * 64 + k];
                v = s;
            } else v = W_mlp[n * 192 + k];
        } else if (n == 64) {
            if (k < 64) {
                float s = 0.f;
                #pragma unroll 8
                for (int j = 0; j < 64; ++j) s += W_alpha[j] * W_init[j * 64 + k];
                v = s;
            } else v = W_alpha[k];
        }
        int ks = k >> 3, t = k & 7;
        int pos = F_WBP + n * 216 + ((t < 4) ? (ks * 8 + t) * 2 : (ks * 8 + t - 4) * 2 + 1);
        sm[pos] = tf32f(v);
    }
    if (tid < 65) {
        float s = (tid < 64) ? b_mlp[tid] : b_alpha[0];
        const float* wr = (tid < 64) ? (W_mlp + tid * 192) : W_alpha;
        #pragma unroll 8
        for (int j = 0; j < 64; ++j) s += b_init[j] * wr[j];
        sm[F_BMX + tid] = s;
    }
    __syncthreads();

    // per-thread constants (frag columns c = nt*8 + 2*t4)
    float bi[8][2], bm[8][2];
    #pragma unroll
    for (int nt = 0; nt < 8; ++nt) {
        int c = nt * 8 + 2 * t4;
        bi[nt][0] = b_init[c];      bi[nt][1] = b_init[c + 1];
        bm[nt][0] = sm[F_BMX + c];  bm[nt][1] = sm[F_BMX + c + 1];
    }
    const float bma = sm[F_BMX + 64];
    float* E = sm + F_E + wid * EW;

    const char* eB = (const char*)edge_fts;
    const char* nB = (const char*)node_fts;
    const int ntiles = (n_edges + 31) >> 5;

    for (int wt = blockIdx.x * 12 + wid; wt < ntiles; wt += gridDim.x * 12) {
        const int tb  = wt << 5;
        const int rem = min(32, n_edges - tb);

        // gather indices: lane r owns row r
        int hidx = 0, tidxv = 0;
        if (lane < rem) {
            size_t ep = (size_t)tb + lane;
            if (is64) { hidx = (int)e64[ep]; tidxv = (int)e64[ep + (size_t)n_edges]; }
            else      { hidx = e32[ep];      tidxv = e32[ep + (size_t)n_edges]; }
        }
        // this thread's 4 rows: j=(mt,half): row = mt*16 + half*8 + g_
        uint32_t eO[4], hO[4], tO[4];
        #pragma unroll
        for (int j = 0; j < 4; ++j) {
            int row = (j >> 1) * 16 + (j & 1) * 8 + g_;
            int er  = min(tb + row, n_edges - 1);
            eO[j] = (uint32_t)er * 256u + (uint32_t)t4 * 4u;
            int hi = __shfl_sync(0xffffffffu, hidx,  row);
            int ti = __shfl_sync(0xffffffffu, tidxv, row);
            hO[j] = (uint32_t)hi * 256u + (uint32_t)t4 * 4u;
            tO[j] = (uint32_t)ti * 256u + (uint32_t)t4 * 4u;
        }

        // ---------------- e-GEMM: 32 x 64, K=64 (EDGE @ W1^T) ----------------
        float accE[2][8][4];
        #pragma unroll
        for (int a = 0; a < 2; ++a)
            #pragma unroll
            for (int b = 0; b < 8; ++b)
                #pragma unroll
                for (int c = 0; c < 4; ++c) accE[a][b][c] = 0.f;
        #pragma unroll
        for (int ks = 0; ks < 8; ++ks) {
            const uint32_t kb = (uint32_t)ks * 32u;
            uint32_t a0[4], a1[4];
            a0[0] = ldgu(eB + eO[0] + kb);      a0[1] = ldgu(eB + eO[1] + kb);
            a0[2] = ldgu(eB + eO[0] + kb + 16); a0[3] = ldgu(eB + eO[1] + kb + 16);
            a1[0] = ldgu(eB + eO[2] + kb);      a1[1] = ldgu(eB + eO[3] + kb);
            a1[2] = ldgu(eB + eO[2] + kb + 16); a1[3] = ldgu(eB + eO[3] + kb + 16);
            #pragma unroll
            for (int nt = 0; nt < 8; ++nt) {
                float2 bb = *(const float2*)&sm[F_W1P + (nt * 8 + g_) * 88 + (ks * 8 + t4) * 2];
                uint32_t b2[2] = { __float_as_uint(bb.x), __float_as_uint(bb.y) };
                mma_tf32(accE[0][nt], a0, b2);
                mma_tf32(accE[1][nt], a1, b2);
            }
        }
        // spill e (+b_init) to per-warp smem (same-thread RAW; no sync needed)
        #pragma unroll
        for (int mt = 0; mt < 2; ++mt)
            #pragma unroll
            for (int nt = 0; nt < 8; ++nt) {
                const int c = nt * 8 + 2 * t4;
                *(float2*)&E[(mt * 16 + g_) * 72 + c] =
                    make_float2(accE[mt][nt][0] + bi[nt][0], accE[mt][nt][1] + bi[nt][1]);
                *(float2*)&E[(mt * 16 + 8 + g_) * 72 + c] =
                    make_float2(accE[mt][nt][2] + bi[nt][0], accE[mt][nt][3] + bi[nt][1]);
            }

        // ---------------- big-GEMM: 32 x 72, K=192 ([EDGE|HEAD|TAIL] @ Wbig^T) ----------------
        float accB[2][9][4];
        #pragma unroll
        for (int a = 0; a < 2; ++a)
            #pragma unroll
            for (int b = 0; b < 9; ++b)
                #pragma unroll
                for (int c = 0; c < 4; ++c) accB[a][b][c] = 0.f;
        #pragma unroll
        for (int pass = 0; pass < 3; ++pass) {
            const char* base = (pass == 0) ? eB : nB;
            const uint32_t* O = (pass == 0) ? eO : (pass == 1) ? hO : tO;
            #pragma unroll
            for (int ks = 0; ks < 8; ++ks) {
                const uint32_t kb = (uint32_t)ks * 32u;
                const int kg = pass * 8 + ks;
                uint32_t a0[4], a1[4];
                a0[0] = ldgu(base + O[0] + kb);      a0[1] = ldgu(base + O[1] + kb);
                a0[2] = ldgu(base + O[0] + kb + 16); a0[3] = ldgu(base + O[1] + kb + 16);
                a1[0] = ldgu(base + O[2] + kb);      a1[1] = ldgu(base + O[3] + kb);
                a1[2] = ldgu(base + O[2] + kb + 16); a1[3] = ldgu(base + O[3] + kb + 16);
                #pragma unroll
                for (int nt = 0; nt < 9; ++nt) {
                    float2 bb = *(const float2*)&sm[F_WBP + (nt * 8 + g_) * 216 + (kg * 8 + t4) * 2];
                    uint32_t b2[2] = { __float_as_uint(bb.x), __float_as_uint(bb.y) };
                    mma_tf32(accB[0][nt], a0, b2);
                    mma_tf32(accB[1][nt], a1, b2);
                }
            }
        }

        // ---------------- epilogue (fragment layout; quad = row) ----------------
        #pragma unroll
        for (int j = 0; j < 4; ++j) {
            const int mt = j >> 1, hf = j & 1;
            const int row = mt * 16 + hf * 8 + g_;
            float p[16];
            float s1 = 0.f, s2 = 0.f;
            #pragma unroll
            for (int nt = 0; nt < 8; ++nt) {
                #pragma unroll
                for (int d = 0; d < 2; ++d) {
                    float pre = accB[mt][nt][hf * 2 + d] + bm[nt][d];
                    float tt  = __expf(-2.f * fabsf(pre));
                    float th  = copysignf(__fdividef(1.f - tt, 1.f + tt), pre);
                    p[nt * 2 + d] = th;
                    s1 += th; s2 += th * th;
                }
            }
            s1 += __shfl_xor_sync(0xffffffffu, s1, 1);
            s1 += __shfl_xor_sync(0xffffffffu, s1, 2);
            s2 += __shfl_xor_sync(0xffffffffu, s2, 1);
            s2 += __shfl_xor_sync(0xffffffffu, s2, 2);
            float ap = accB[mt][8][hf * 2] + bma;        // col 64 lives at t4==0
            ap = __shfl_sync(0xffffffffu, ap, lane & ~3);
            const float alpha = __fdividef(1.f, 1.f + __expf(-ap));
            const float mean  = s1 * (1.f / 64.f);
            const float var   = s2 * (1.f / 64.f) - mean * mean;
            const float rstd  = rsqrtf(var + LN_EPS) * alpha;

            float y[16];
            float u1 = 0.f, u2 = 0.f;
            #pragma unroll
            for (int nt = 0; nt < 8; ++nt) {
                float2 ev = *(const float2*)&E[row * 72 + nt * 8 + 2 * t4];
                float y0 = ev.x + (p[nt * 2 + 0] - mean) * rstd;
                float y1 = ev.y + (p[nt * 2 + 1] - mean) * rstd;
                y[nt * 2 + 0] = y0; y[nt * 2 + 1] = y1;
                u1 += y0 + y1; u2 += y0 * y0 + y1 * y1;
            }
            u1 += __shfl_xor_sync(0xffffffffu, u1, 1);
            u1 += __shfl_xor_sync(0xffffffffu, u1, 2);
            u2 += __shfl_xor_sync(0xffffffffu, u2, 1);
            u2 += __shfl_xor_sync(0xffffffffu, u2, 2);
            const float m2  = u1 * (1.f / 64.f);
            const float v2  = u2 * (1.f / 64.f) - m2 * m2;
            const float rs2 = rsqrtf(v2 + LN_EPS);

            if (row < rem) {
                float2* op = (float2*)(out + (size_t)(tb + row) * 64) + t4;
                #pragma unroll
                for (int nt = 0; nt < 8; ++nt)
                    op[nt * 4] = make_float2((y[nt * 2] - m2) * rs2, (y[nt * 2 + 1] - m2) * rs2);
            }
        }
    }
}

extern "C" void kernel_launch(void* const* d_in, const int* in_sizes, int n_in,
                              void* d_out, int out_size)
{
    const float* node_fts = (const float*)d_in[0];
    const float* edge_fts = (const float*)d_in[1];
    const void*  edges    = d_in[2];
    const float* W_init   = (const float*)d_in[3];
    const float* b_init   = (const float*)d_in[4];
    const float* W_mlp    = (const float*)d_in[5];
    const float* b_mlp    = (const float*)d_in[6];
    const float* W_alpha  = (const float*)d_in[7];
    const float* b_alpha  = (const float*)d_in[8];
    float*       out      = (float*)d_out;

    const int n_edges = in_sizes[1] / 64;
    const int ntiles  = (n_edges + 31) / 32;

    int nsm = 148;
    cudaDeviceGetAttribute(&nsm, cudaDevAttrMultiProcessorCount, 0);
    int need = (ntiles + 11) / 12;
    int grid = need < nsm ? need : nsm;

    cudaFuncSetAttribute(edge_update_v6,
                         cudaFuncAttributeMaxDynamicSharedMemorySize, SMEM_BYTES);
    probe_edges_dtype<<<1, 32>>>((const long long*)edges);
    edge_update_v6<<<grid, NT, SMEM_BYTES>>>(
        node_fts, edge_fts, edges, W_init, b_init,
        W_mlp, b_mlp, W_alpha, b_alpha, out, n_edges);
}

// round 7
// speedup vs baseline: 2.1093x; 1.1088x over previous
#include <cuda_runtime.h>
#include <cstdint>

#define NT 256
#define LN_EPS 1e-5f

// smem float offsets
#define F_W1P 0                // W1 packed: 64 rows x stride 80
#define F_WBP 5120             // Wbig packed: 72 rows x stride 208
#define F_BI  20096            // b_init (actual order) [64]
#define F_BMX 20160            // folded bias (actual order) [65] + pad
#define SM_FLOATS 20228
#define SMEM_BYTES (SM_FLOATS * 4)

__device__ int g_edges_is_i64;

__global__ void probe_edges_dtype(const long long* __restrict__ e64) {
    if (threadIdx.x == 0) {
        int ok = 1;
        for (int i = 0; i < 64; ++i) {
            long long v = e64[i];
            if (v < 0 || v >= (1LL << 31)) ok = 0;
        }
        g_edges_is_i64 = ok;
    }
}

__device__ __forceinline__ float tf32f(float x) {
    uint32_t u; asm("cvt.rna.tf32.f32 %0, %1;" : "=r"(u) : "f"(x));
    return __uint_as_float(u);
}
// N-permutation: logical frag col -> actual col (so each thread's 16 cols = 4 float4s)
__device__ __forceinline__ int sigp(int c) {
    return 16 * (c >> 4) + 4 * ((c & 7) >> 1) + 2 * ((c >> 3) & 1) + (c & 1);
}
// K-permutation packing position for orig k within a row: j=k>>4 group, float4-friendly
__device__ __forceinline__ int kpos(int k) {
    return ((k >> 4) * 4 + ((k >> 2) & 3)) * 4 + (k & 3);
}
#define U(x) __float_as_uint(x)
__device__ __forceinline__ void mma_t(float c[4], uint32_t a0, uint32_t a1, uint32_t a2,
                                      uint32_t a3, uint32_t b0, uint32_t b1) {
    asm volatile(
        "mma.sync.aligned.m16n8k8.row.col.f32.tf32.tf32.f32 "
        "{%0,%1,%2,%3}, {%4,%5,%6,%7}, {%8,%9}, {%0,%1,%2,%3};\n"
        : "+f"(c[0]), "+f"(c[1]), "+f"(c[2]), "+f"(c[3])
        : "r"(a0), "r"(a1), "r"(a2), "r"(a3), "r"(b0), "r"(b1));
}

__global__ void __launch_bounds__(NT, 1)
edge_update_v7(const float* __restrict__ node_fts,
               const float* __restrict__ edge_fts,
               const void* __restrict__ edges_raw,
               const float* __restrict__ W_init,
               const float* __restrict__ b_init,
               const float* __restrict__ W_mlp,
               const float* __restrict__ b_mlp,
               const float* __restrict__ W_alpha,
               const float* __restrict__ b_alpha,
               float* __restrict__ out,
               int n_edges)
{
    extern __shared__ float sm[];
    const int tid  = threadIdx.x;
    const int is64 = g_edges_is_i64;
    const long long* e64 = (const long long*)edges_raw;
    const int*       e32 = (const int*)edges_raw;

    // ---------------- one-time setup: permuted weight packing ----------------
    for (int i = tid; i < 64 * 64; i += NT) {
        int c = i >> 6, k = i & 63;
        sm[F_W1P + c * 80 + kpos(k)] = tf32f(W_init[sigp(c) * 64 + k]);
    }
    for (int i = tid; i < 72 * 192; i += NT) {
        int c = i / 192, k = i - c * 192;
        float v = 0.f;
        if (c < 64) {
            int a = sigp(c);
            if (k < 64) {
                float s = 0.f;
                #pragma unroll 8
                for (int m = 0; m < 64; ++m) s += W_mlp[a * 192 + m] * W_init[m * 64 + k];
                v = s;
            } else v = W_mlp[a * 192 + k];
        } else if (c == 64) {
            if (k < 64) {
                float s = 0.f;
                #pragma unroll 8
                for (int m = 0; m < 64; ++m) s += W_alpha[m] * W_init[m * 64 + k];
                v = s;
            } else v = W_alpha[k];
        }
        sm[F_WBP + c * 208 + kpos(k)] = tf32f(v);
    }
    if (tid < 64) sm[F_BI + tid] = b_init[tid];
    if (tid < 65) {
        float s = (tid < 64) ? b_mlp[tid] : b_alpha[0];
        const float* wr = (tid < 64) ? (W_mlp + tid * 192) : W_alpha;
        #pragma unroll 8
        for (int m = 0; m < 64; ++m) s += b_init[m] * wr[m];
        sm[F_BMX + tid] = s;
    }
    __syncthreads();

    const int wid  = tid >> 5;
    const int lane = tid & 31;
    const int g_   = lane >> 2;
    const int t4   = lane & 3;
    const float bma = sm[F_BMX + 64];

    const char* eB = (const char*)edge_fts;
    const char* nB = (const char*)node_fts;
    const int ntiles = (n_edges + 31) >> 5;

#define LD4(s, r) __ldg((const float4*)( (((s) >> 2) ? nB : eB) \
        + (((s) >> 2) == 0 ? eO[r] : (((s) >> 2) == 1 ? hO[r] : tO[r])) \
        + (uint32_t)(((s) & 3) * 64) ))

    for (int wt = blockIdx.x * 8 + wid; wt < ntiles; wt += gridDim.x * 8) {
        const int tb  = wt << 5;
        const int rem = min(32, n_edges - tb);

        int hidx = 0, tidx = 0;
        if (lane < rem) {
            size_t ep = (size_t)tb + lane;
            if (is64) { hidx = (int)e64[ep]; tidx = (int)e64[ep + (size_t)n_edges]; }
            else      { hidx = e32[ep];      tidx = e32[ep + (size_t)n_edges]; }
        }
        uint32_t eO[4], hO[4], tO[4];
        #pragma unroll
        for (int r = 0; r < 4; ++r) {
            int row = (r >> 1) * 16 + (r & 1) * 8 + g_;
            int er  = min(tb + row, n_edges - 1);
            eO[r] = (uint32_t)er * 256u + (uint32_t)t4 * 16u;
            int hi = __shfl_sync(0xffffffffu, hidx, row);
            int ti = __shfl_sync(0xffffffffu, tidx, row);
            hO[r] = (uint32_t)hi * 256u + (uint32_t)t4 * 16u;
            tO[r] = (uint32_t)ti * 256u + (uint32_t)t4 * 16u;
        }

        float accE[2][8][4], accB[2][9][4];
        #pragma unroll
        for (int a = 0; a < 2; ++a) {
            #pragma unroll
            for (int b = 0; b < 8; ++b)
                #pragma unroll
                for (int c = 0; c < 4; ++c) accE[a][b][c] = 0.f;
            #pragma unroll
            for (int b = 0; b < 9; ++b)
                #pragma unroll
                for (int c = 0; c < 4; ++c) accB[a][b][c] = 0.f;
        }

        float4 vc0 = LD4(0, 0), vc1 = LD4(0, 1), vc2 = LD4(0, 2), vc3 = LD4(0, 3);
        #pragma unroll
        for (int s = 0; s < 12; ++s) {
            float4 vn0, vn1, vn2, vn3;
            if (s < 11) { vn0 = LD4(s + 1, 0); vn1 = LD4(s + 1, 1);
                          vn2 = LD4(s + 1, 2); vn3 = LD4(s + 1, 3); }
            const int wo = (s * 4 + t4) * 4;
            #pragma unroll
            for (int nt = 0; nt < 9; ++nt) {
                float4 w = *(const float4*)&sm[F_WBP + (nt * 8 + g_) * 208 + wo];
                mma_t(accB[0][nt], U(vc0.x), U(vc1.x), U(vc0.y), U(vc1.y), U(w.x), U(w.y));
                mma_t(accB[1][nt], U(vc2.x), U(vc3.x), U(vc2.y), U(vc3.y), U(w.x), U(w.y));
                mma_t(accB[0][nt], U(vc0.z), U(vc1.z), U(vc0.w), U(vc1.w), U(w.z), U(w.w));
                mma_t(accB[1][nt], U(vc2.z), U(vc3.z), U(vc2.w), U(vc3.w), U(w.z), U(w.w));
            }
            if (s < 4) {
                #pragma unroll
                for (int nt = 0; nt < 8; ++nt) {
                    float4 w = *(const float4*)&sm[F_W1P + (nt * 8 + g_) * 80 + wo];
                    mma_t(accE[0][nt], U(vc0.x), U(vc1.x), U(vc0.y), U(vc1.y), U(w.x), U(w.y));
                    mma_t(accE[1][nt], U(vc2.x), U(vc3.x), U(vc2.y), U(vc3.y), U(w.x), U(w.y));
                    mma_t(accE[0][nt], U(vc0.z), U(vc1.z), U(vc0.w), U(vc1.w), U(w.z), U(w.w));
                    mma_t(accE[1][nt], U(vc2.z), U(vc3.z), U(vc2.w), U(vc3.w), U(w.z), U(w.w));
                }
            }
            if (s < 11) { vc0 = vn0; vc1 = vn1; vc2 = vn2; vc3 = vn3; }
        }

        // ---------------- epilogue (all in registers; actual-col float4 groups) ----------------
        #pragma unroll
        for (int jj = 0; jj < 4; ++jj) {
            const int mt = jj >> 1, h2 = (jj & 1) * 2;
            const int row = mt * 16 + (jj & 1) * 8 + g_;

            float p[16], s1 = 0.f, s2 = 0.f;
            #pragma unroll
            for (int J = 0; J < 4; ++J) {
                float4 bm4 = *(const float4*)&sm[F_BMX + J * 16 + t4 * 4];
                float pre[4] = { accB[mt][2 * J][h2] + bm4.x,
                                 accB[mt][2 * J][h2 + 1] + bm4.y,
                                 accB[mt][2 * J + 1][h2] + bm4.z,
                                 accB[mt][2 * J + 1][h2 + 1] + bm4.w };
                #pragma unroll
                for (int c = 0; c < 4; ++c) {
                    float th = 1.f - __fdividef(2.f, __expf(2.f * pre[c]) + 1.f);
                    p[J * 4 + c] = th;
                    s1 += th; s2 += th * th;
                }
            }
            s1 += __shfl_xor_sync(0xffffffffu, s1, 1);
            s1 += __shfl_xor_sync(0xffffffffu, s1, 2);
            s2 += __shfl_xor_sync(0xffffffffu, s2, 1);
            s2 += __shfl_xor_sync(0xffffffffu, s2, 2);
            float ap = accB[mt][8][h2] + bma;
            ap = __shfl_sync(0xffffffffu, ap, lane & ~3);
            const float alpha = __fdividef(1.f, 1.f + __expf(-ap));
            const float mean  = s1 * (1.f / 64.f);
            const float var   = s2 * (1.f / 64.f) - mean * mean;
            const float rstd  = rsqrtf(var + LN_EPS) * alpha;

            float y[16], u1 = 0.f, u2 = 0.f;
            #pragma unroll
            for (int J = 0; J < 4; ++J) {
                float4 bi4 = *(const float4*)&sm[F_BI + J * 16 + t4 * 4];
                float e0 = accE[mt][2 * J][h2] + bi4.x;
                float e1 = accE[mt][2 * J][h2 + 1] + bi4.y;
                float e2 = accE[mt][2 * J + 1][h2] + bi4.z;
                float e3 = accE[mt][2 * J + 1][h2 + 1] + bi4.w;
                float y0 = e0 + (p[J * 4 + 0] - mean) * rstd;
                float y1 = e1 + (p[J * 4 + 1] - mean) * rstd;
                float y2 = e2 + (p[J * 4 + 2] - mean) * rstd;
                float y3 = e3 + (p[J * 4 + 3] - mean) * rstd;
                y[J * 4 + 0] = y0; y[J * 4 + 1] = y1; y[J * 4 + 2] = y2; y[J * 4 + 3] = y3;
                u1 += y0 + y1 + y2 + y3;
                u2 += y0 * y0 + y1 * y1 + y2 * y2 + y3 * y3;
            }
            u1 += __shfl_xor_sync(0xffffffffu, u1, 1);
            u1 += __shfl_xor_sync(0xffffffffu, u1, 2);
            u2 += __shfl_xor_sync(0xffffffffu, u2, 1);
            u2 += __shfl_xor_sync(0xffffffffu, u2, 2);
            const float m2  = u1 * (1.f / 64.f);
            const float v2  = u2 * (1.f / 64.f) - m2 * m2;
            const float rs2 = rsqrtf(v2 + LN_EPS);

            if (row < rem) {
                float* op = out + (size_t)(tb + row) * 64;
                #pragma unroll
                for (int J = 0; J < 4; ++J) {
                    float4 o;
                    o.x = (y[J * 4 + 0] - m2) * rs2;
                    o.y = (y[J * 4 + 1] - m2) * rs2;
                    o.z = (y[J * 4 + 2] - m2) * rs2;
                    o.w = (y[J * 4 + 3] - m2) * rs2;
                    *(float4*)(op + J * 16 + t4 * 4) = o;
                }
            }
        }
    }
#undef LD4
}

extern "C" void kernel_launch(void* const* d_in, const int* in_sizes, int n_in,
                              void* d_out, int out_size)
{
    const float* node_fts = (const float*)d_in[0];
    const float* edge_fts = (const float*)d_in[1];
    const void*  edges    = d_in[2];
    const float* W_init   = (const float*)d_in[3];
    const float* b_init   = (const float*)d_in[4];
    const float* W_mlp    = (const float*)d_in[5];
    const float* b_mlp    = (const float*)d_in[6];
    const float* W_alpha  = (const float*)d_in[7];
    const float* b_alpha  = (const float*)d_in[8];
    float*       out      = (float*)d_out;

    const int n_edges = in_sizes[1] / 64;
    const int ntiles  = (n_edges + 31) / 32;

    int nsm = 148;
    cudaDeviceGetAttribute(&nsm, cudaDevAttrMultiProcessorCount, 0);
    int need = (ntiles + 7) / 8;
    int grid = need < nsm ? need : nsm;

    cudaFuncSetAttribute(edge_update_v7,
                         cudaFuncAttributeMaxDynamicSharedMemorySize, SMEM_BYTES);
    probe_edges_dtype<<<1, 32>>>((const long long*)edges);
    edge_update_v7<<<grid, NT, SMEM_BYTES>>>(
        node_fts, edge_fts, edges, W_init, b_init,
        W_mlp, b_mlp, W_alpha, b_alpha, out, n_edges);
}

// round 8
// speedup vs baseline: 2.8398x; 1.3464x over previous
#include <cuda_runtime.h>
#include <cstdint>

#define NT 256
#define LN_EPS 1e-5f

// packed-weight layout (floats), shared by g_wpack and smem
#define F_W1P 0                 // W1 packed: 64 cols x stride 80
#define F_WBP 5120              // Wbig packed: 72 cols x stride 208
#define F_BI  20096             // b_init [64]
#define F_BMX 20160             // folded bias [65] + pad
#define SM_FLOATS 20228
#define SMEM_BYTES (SM_FLOATS * 4)

__device__ int   g_edges_is_i64;
__device__ float g_wpack[SM_FLOATS];

__device__ __forceinline__ float tf32f(float x) {
    uint32_t u; asm("cvt.rna.tf32.f32 %0, %1;" : "=r"(u) : "f"(x));
    return __uint_as_float(u);
}
// N-permutation: logical frag col -> actual col (thread's 16 cols = 4 float4s)
__device__ __forceinline__ int sigp(int c) {
    return 16 * (c >> 4) + 4 * ((c & 7) >> 1) + 2 * ((c >> 3) & 1) + (c & 1);
}
// K-permutation packing position (A-side reads raw float4s; B repacked to match)
__device__ __forceinline__ int kpos(int k) {
    return ((k >> 4) * 4 + ((k >> 2) & 3)) * 4 + (k & 3);
}

__global__ void probe_edges_dtype(const long long* __restrict__ e64) {
    if (threadIdx.x == 0) {
        int ok = 1;
        for (int i = 0; i < 64; ++i) {
            long long v = e64[i];
            if (v < 0 || v >= (1LL << 31)) ok = 0;
        }
        g_edges_is_i64 = ok;
    }
}

__global__ void prep_weights(const float* __restrict__ W_init,
                             const float* __restrict__ b_init,
                             const float* __restrict__ W_mlp,
                             const float* __restrict__ b_mlp,
                             const float* __restrict__ W_alpha,
                             const float* __restrict__ b_alpha)
{
    int i = blockIdx.x * blockDim.x + threadIdx.x;
    if (i < 64 * 64) {
        int c = i >> 6, k = i & 63;
        g_wpack[F_W1P + c * 80 + kpos(k)] = tf32f(W_init[sigp(c) * 64 + k]);
    } else if (i < 64 * 64 + 72 * 192) {
        int j = i - 64 * 64;
        int c = j / 192, k = j - c * 192;
        float v = 0.f;
        if (c < 64) {
            int a = sigp(c);
            if (k < 64) {
                float s = 0.f;
                #pragma unroll 8
                for (int m = 0; m < 64; ++m) s += W_mlp[a * 192 + m] * W_init[m * 64 + k];
                v = s;
            } else v = W_mlp[a * 192 + k];
        } else if (c == 64) {
            if (k < 64) {
                float s = 0.f;
                #pragma unroll 8
                for (int m = 0; m < 64; ++m) s += W_alpha[m] * W_init[m * 64 + k];
                v = s;
            } else v = W_alpha[k];
        }
        g_wpack[F_WBP + c * 208 + kpos(k)] = tf32f(v);
    } else if (i < 64 * 64 + 72 * 192 + 64) {
        int t = i - (64 * 64 + 72 * 192);
        g_wpack[F_BI + t] = b_init[t];
    } else if (i < 64 * 64 + 72 * 192 + 64 + 65) {
        int t = i - (64 * 64 + 72 * 192 + 64);
        float s = (t < 64) ? b_mlp[t] : b_alpha[0];
        const float* wr = (t < 64) ? (W_mlp + t * 192) : W_alpha;
        #pragma unroll 8
        for (int m = 0; m < 64; ++m) s += b_init[m] * wr[m];
        g_wpack[F_BMX + t] = s;
    }
}

#define U(x) __float_as_uint(x)
__device__ __forceinline__ void mma_t(float c[4], uint32_t a0, uint32_t a1, uint32_t a2,
                                      uint32_t a3, uint32_t b0, uint32_t b1) {
    asm volatile(
        "mma.sync.aligned.m16n8k8.row.col.f32.tf32.tf32.f32 "
        "{%0,%1,%2,%3}, {%4,%5,%6,%7}, {%8,%9}, {%0,%1,%2,%3};\n"
        : "+f"(c[0]), "+f"(c[1]), "+f"(c[2]), "+f"(c[3])
        : "r"(a0), "r"(a1), "r"(a2), "r"(a3), "r"(b0), "r"(b1));
}

__global__ void __launch_bounds__(NT, 2)
edge_update_v8(const float* __restrict__ node_fts,
               const float* __restrict__ edge_fts,
               const void* __restrict__ edges_raw,
               float* __restrict__ out,
               int n_edges)
{
    extern __shared__ float sm[];
    const int tid = threadIdx.x;
    // copy packed weights (coalesced, L2-hot after first CTA wave)
    for (int i = tid; i < SM_FLOATS; i += NT) sm[i] = g_wpack[i];
    __syncthreads();

    const int wid  = tid >> 5;
    const int lane = tid & 31;
    const int g_   = lane >> 2;
    const int t4   = lane & 3;
    const int is64 = g_edges_is_i64;
    const long long* e64 = (const long long*)edges_raw;
    const int*       e32 = (const int*)edges_raw;
    const float bma = sm[F_BMX + 64];

    const char* eB = (const char*)edge_fts;
    const char* nB = (const char*)node_fts;
    const int ntiles = (n_edges + 15) >> 4;

    for (int wt = blockIdx.x * 8 + wid; wt < ntiles; wt += gridDim.x * 8) {
        const int tb  = wt << 4;
        const int rem = min(16, n_edges - tb);

        // tile indices: lane r (<16) holds row r's head/tail index
        int hidx = 0, tidx = 0;
        if (lane < 16) {
            size_t ep = (size_t)min(tb + lane, n_edges - 1);
            if (is64) { hidx = (int)e64[ep]; tidx = (int)e64[ep + (size_t)n_edges]; }
            else      { hidx = e32[ep];      tidx = e32[ep + (size_t)n_edges]; }
        }
        // full row pointers (fold all address math here)
        const char* pA[3][2];
        #pragma unroll
        for (int r = 0; r < 2; ++r) {
            const int row = r * 8 + g_;
            const int er  = min(tb + row, n_edges - 1);
            pA[0][r] = eB + (size_t)er * 256 + (size_t)(t4 * 16);
            const int hi = __shfl_sync(0xffffffffu, hidx, row);
            const int ti = __shfl_sync(0xffffffffu, tidx, row);
            pA[1][r] = nB + (size_t)hi * 256 + (size_t)(t4 * 16);
            pA[2][r] = nB + (size_t)ti * 256 + (size_t)(t4 * 16);
        }

        float accE[8][4], accB[9][4];
        #pragma unroll
        for (int b = 0; b < 8; ++b)
            #pragma unroll
            for (int c = 0; c < 4; ++c) accE[b][c] = 0.f;
        #pragma unroll
        for (int b = 0; b < 9; ++b)
            #pragma unroll
            for (int c = 0; c < 4; ++c) accB[b][c] = 0.f;

        float4 vc0 = __ldg((const float4*)pA[0][0]);
        float4 vc1 = __ldg((const float4*)pA[0][1]);
        #pragma unroll
        for (int s = 0; s < 12; ++s) {
            float4 vn0, vn1;
            if (s < 11) {
                const int sp = s + 1;
                vn0 = __ldg((const float4*)(pA[sp >> 2][0] + (sp & 3) * 64));
                vn1 = __ldg((const float4*)(pA[sp >> 2][1] + (sp & 3) * 64));
            }
            const int wo = (s * 4 + t4) * 4;
            #pragma unroll
            for (int nt = 0; nt < 9; ++nt) {
                float4 w = *(const float4*)&sm[F_WBP + (nt * 8 + g_) * 208 + wo];
                mma_t(accB[nt], U(vc0.x), U(vc1.x), U(vc0.y), U(vc1.y), U(w.x), U(w.y));
                mma_t(accB[nt], U(vc0.z), U(vc1.z), U(vc0.w), U(vc1.w), U(w.z), U(w.w));
            }
            if (s < 4) {
                #pragma unroll
                for (int nt = 0; nt < 8; ++nt) {
                    float4 w = *(const float4*)&sm[F_W1P + (nt * 8 + g_) * 80 + wo];
                    mma_t(accE[nt], U(vc0.x), U(vc1.x), U(vc0.y), U(vc1.y), U(w.x), U(w.y));
                    mma_t(accE[nt], U(vc0.z), U(vc1.z), U(vc0.w), U(vc1.w), U(w.z), U(w.w));
                }
            }
            if (s < 11) { vc0 = vn0; vc1 = vn1; }
        }

        // ---------------- epilogue (registers only) ----------------
        #pragma unroll
        for (int hf = 0; hf < 2; ++hf) {
            const int h2  = hf * 2;
            const int row = hf * 8 + g_;

            float p[16], s1 = 0.f, s2 = 0.f;
            #pragma unroll
            for (int J = 0; J < 4; ++J) {
                float4 bm4 = *(const float4*)&sm[F_BMX + J * 16 + t4 * 4];
                float pre[4] = { accB[2 * J][h2]     + bm4.x,
                                 accB[2 * J][h2 + 1] + bm4.y,
                                 accB[2 * J + 1][h2]     + bm4.z,
                                 accB[2 * J + 1][h2 + 1] + bm4.w };
                #pragma unroll
                for (int c = 0; c < 4; ++c) {
                    float th = 1.f - __fdividef(2.f, __expf(2.f * pre[c]) + 1.f);
                    p[J * 4 + c] = th;
                    s1 += th; s2 += th * th;
                }
            }
            s1 += __shfl_xor_sync(0xffffffffu, s1, 1);
            s1 += __shfl_xor_sync(0xffffffffu, s1, 2);
            s2 += __shfl_xor_sync(0xffffffffu, s2, 1);
            s2 += __shfl_xor_sync(0xffffffffu, s2, 2);
            float ap = accB[8][h2] + bma;
            ap = __shfl_sync(0xffffffffu, ap, lane & ~3);
            const float alpha = __fdividef(1.f, 1.f + __expf(-ap));
            const float mean  = s1 * (1.f / 64.f);
            const float var   = s2 * (1.f / 64.f) - mean * mean;
            const float rstd  = rsqrtf(var + LN_EPS) * alpha;

            float y[16], u1 = 0.f, u2 = 0.f;
            #pragma unroll
            for (int J = 0; J < 4; ++J) {
                float4 bi4 = *(const float4*)&sm[F_BI + J * 16 + t4 * 4];
                float y0 = accE[2 * J][h2]     + bi4.x + (p[J * 4 + 0] - mean) * rstd;
                float y1 = accE[2 * J][h2 + 1] + bi4.y + (p[J * 4 + 1] - mean) * rstd;
                float y2 = accE[2 * J + 1][h2]     + bi4.z + (p[J * 4 + 2] - mean) * rstd;
                float y3 = accE[2 * J + 1][h2 + 1] + bi4.w + (p[J * 4 + 3] - mean) * rstd;
                y[J * 4 + 0] = y0; y[J * 4 + 1] = y1; y[J * 4 + 2] = y2; y[J * 4 + 3] = y3;
                u1 += y0 + y1 + y2 + y3;
                u2 += y0 * y0 + y1 * y1 + y2 * y2 + y3 * y3;
            }
            u1 += __shfl_xor_sync(0xffffffffu, u1, 1);
            u1 += __shfl_xor_sync(0xffffffffu, u1, 2);
            u2 += __shfl_xor_sync(0xffffffffu, u2, 1);
            u2 += __shfl_xor_sync(0xffffffffu, u2, 2);
            const float m2  = u1 * (1.f / 64.f);
            const float v2  = u2 * (1.f / 64.f) - m2 * m2;
            const float rs2 = rsqrtf(v2 + LN_EPS);

            if (row < rem) {
                float* op = out + (size_t)(tb + row) * 64;
                #pragma unroll
                for (int J = 0; J < 4; ++J) {
                    float4 o;
                    o.x = (y[J * 4 + 0] - m2) * rs2;
                    o.y = (y[J * 4 + 1] - m2) * rs2;
                    o.z = (y[J * 4 + 2] - m2) * rs2;
                    o.w = (y[J * 4 + 3] - m2) * rs2;
                    *(float4*)(op + J * 16 + t4 * 4) = o;
                }
            }
        }
    }
}

extern "C" void kernel_launch(void* const* d_in, const int* in_sizes, int n_in,
                              void* d_out, int out_size)
{
    const float* node_fts = (const float*)d_in[0];
    const float* edge_fts = (const float*)d_in[1];
    const void*  edges    = d_in[2];
    const float* W_init   = (const float*)d_in[3];
    const float* b_init   = (const float*)d_in[4];
    const float* W_mlp    = (const float*)d_in[5];
    const float* b_mlp    = (const float*)d_in[6];
    const float* W_alpha  = (const float*)d_in[7];
    const float* b_alpha  = (const float*)d_in[8];
    float*       out      = (float*)d_out;

    const int n_edges = in_sizes[1] / 64;
    const int ntiles  = (n_edges + 15) / 16;

    int nsm = 148;
    cudaDeviceGetAttribute(&nsm, cudaDevAttrMultiProcessorCount, 0);
    int need = (ntiles + 7) / 8;
    int maxg = 2 * nsm;
    int grid = need < maxg ? need : maxg;

    cudaFuncSetAttribute(edge_update_v8,
                         cudaFuncAttributeMaxDynamicSharedMemorySize, SMEM_BYTES);
    probe_edges_dtype<<<1, 32>>>((const long long*)edges);
    prep_weights<<<71, 256>>>(W_init, b_init, W_mlp, b_mlp, W_alpha, b_alpha);
    edge_update_v8<<<grid, NT, SMEM_BYTES>>>(node_fts, edge_fts, edges, out, n_edges);
}

// round 9
// speedup vs baseline: 4.0551x; 1.4279x over previous
#include <cuda_runtime.h>
#include <cuda_fp16.h>
#include <cstdint>

#define NT 256
#define LN_EPS 1e-5f

// smem byte offsets
#define SB_W1  0          // __half W1 packed: 64 cols x stride 80 halves  = 10240 B
#define SB_WB  10240      // __half Wbig packed: 72 cols x stride 208 halves = 29952 B
#define SB_BI  40192      // float b_init [64]
#define SB_BMX 40448      // float folded bias [65]+pad
#define SMEM_BYTES 40720

__device__ int    g_edges_is_i64;
__device__ __half g_w1[64 * 80];
__device__ __half g_wb[72 * 208];
__device__ float  g_bi[64];
__device__ float  g_bmx[68];

// N-permutation: logical frag col -> actual col (thread's 16 cols = 4 float4s)
__device__ __host__ __forceinline__ int sigp(int c) {
    return 16 * (c >> 4) + 4 * ((c & 7) >> 1) + 2 * ((c >> 3) & 1) + (c & 1);
}

__global__ void prep_all(const float* __restrict__ W_init,
                         const float* __restrict__ b_init,
                         const float* __restrict__ W_mlp,
                         const float* __restrict__ b_mlp,
                         const float* __restrict__ W_alpha,
                         const float* __restrict__ b_alpha,
                         const long long* __restrict__ e64)
{
    int i = blockIdx.x * blockDim.x + threadIdx.x;
    if (i == 0) {
        int ok = 1;
        for (int j = 0; j < 64; ++j) {
            long long v = e64[j];
            if (v < 0 || v >= (1LL << 31)) ok = 0;
        }
        g_edges_is_i64 = ok;
    }
    if (i < 64 * 64) {
        int c = i >> 6, k = i & 63;
        g_w1[c * 80 + k] = __float2half_rn(W_init[sigp(c) * 64 + k]);
    } else if (i < 64 * 64 + 72 * 192) {
        int j = i - 64 * 64;
        int c = j / 192, k = j - c * 192;
        float v = 0.f;
        if (c < 64) {
            int a = sigp(c);
            if (k < 64) {
                float s = 0.f;
                #pragma unroll 8
                for (int m = 0; m < 64; ++m) s += W_mlp[a * 192 + m] * W_init[m * 64 + k];
                v = s;
            } else v = W_mlp[a * 192 + k];
        } else if (c == 64) {
            if (k < 64) {
                float s = 0.f;
                #pragma unroll 8
                for (int m = 0; m < 64; ++m) s += W_alpha[m] * W_init[m * 64 + k];
                v = s;
            } else v = W_alpha[k];
        }
        g_wb[c * 208 + k] = __float2half_rn(v);
    } else if (i < 64 * 64 + 72 * 192 + 64) {
        int t = i - (64 * 64 + 72 * 192);
        g_bi[t] = b_init[t];
    } else if (i < 64 * 64 + 72 * 192 + 64 + 65) {
        int t = i - (64 * 64 + 72 * 192 + 64);
        float s = (t < 64) ? b_mlp[t] : b_alpha[0];
        const float* wr = (t < 64) ? (W_mlp + t * 192) : W_alpha;
        #pragma unroll 8
        for (int m = 0; m < 64; ++m) s += b_init[m] * wr[m];
        g_bmx[t] = s;
    }
}

__device__ __forceinline__ uint32_t H2(float a, float b) {
    __half2 h = __floats2half2_rn(a, b);
    return *(uint32_t*)&h;
}
__device__ __forceinline__ void mma_f16(float c[4], uint32_t a0, uint32_t a1, uint32_t a2,
                                        uint32_t a3, uint32_t b0, uint32_t b1) {
    asm volatile(
        "mma.sync.aligned.m16n8k16.row.col.f32.f16.f16.f32 "
        "{%0,%1,%2,%3}, {%4,%5,%6,%7}, {%8,%9}, {%0,%1,%2,%3};\n"
        : "+f"(c[0]), "+f"(c[1]), "+f"(c[2]), "+f"(c[3])
        : "r"(a0), "r"(a1), "r"(a2), "r"(a3), "r"(b0), "r"(b1));
}

__global__ void __launch_bounds__(NT, 2)
edge_update_v9(const float* __restrict__ node_fts,
               const float* __restrict__ edge_fts,
               const void* __restrict__ edges_raw,
               float* __restrict__ out,
               int n_edges)
{
    extern __shared__ char smc[];
    const int tid = threadIdx.x;
    // copy packed weights + biases to smem (coalesced int4 where possible)
    {
        int4* d = (int4*)smc;
        const int4* s1 = (const int4*)g_w1;
        for (int i = tid; i < 10240 / 16; i += NT) d[i] = s1[i];
        int4* d2 = (int4*)(smc + SB_WB);
        const int4* s2 = (const int4*)g_wb;
        for (int i = tid; i < 29952 / 16; i += NT) d2[i] = s2[i];
        float* bf = (float*)(smc + SB_BI);
        if (tid < 64) bf[tid] = g_bi[tid];
        float* bm = (float*)(smc + SB_BMX);
        if (tid < 65) bm[tid] = g_bmx[tid];
    }
    __syncthreads();

    const __half* sw1 = (const __half*)(smc + SB_W1);
    const __half* swb = (const __half*)(smc + SB_WB);
    const float*  sbi = (const float*)(smc + SB_BI);
    const float*  sbm = (const float*)(smc + SB_BMX);

    const int wid  = tid >> 5;
    const int lane = tid & 31;
    const int g_   = lane >> 2;
    const int t4   = lane & 3;
    const int is64 = g_edges_is_i64;
    const long long* e64 = (const long long*)edges_raw;
    const int*       e32 = (const int*)edges_raw;
    const float bma = sbm[64];

    const char* eB = (const char*)edge_fts;
    const char* nB = (const char*)node_fts;
    const int ntiles = (n_edges + 15) >> 4;

    for (int wt = blockIdx.x * 8 + wid; wt < ntiles; wt += gridDim.x * 8) {
        const int tb  = wt << 4;
        const int rem = min(16, n_edges - tb);

        int hidx = 0, tidx = 0;
        if (lane < 16) {
            size_t ep = (size_t)min(tb + lane, n_edges - 1);
            if (is64) { hidx = (int)e64[ep]; tidx = (int)e64[ep + (size_t)n_edges]; }
            else      { hidx = e32[ep];      tidx = e32[ep + (size_t)n_edges]; }
        }
        const char* pA[3][2];
        #pragma unroll
        for (int r = 0; r < 2; ++r) {
            const int row = r * 8 + g_;
            const int er  = min(tb + row, n_edges - 1);
            pA[0][r] = eB + (size_t)er * 256 + (size_t)(t4 * 16);
            const int hi = __shfl_sync(0xffffffffu, hidx, row);
            const int ti = __shfl_sync(0xffffffffu, tidx, row);
            pA[1][r] = nB + (size_t)hi * 256 + (size_t)(t4 * 16);
            pA[2][r] = nB + (size_t)ti * 256 + (size_t)(t4 * 16);
        }

        float accE[8][4], accB[9][4];
        #pragma unroll
        for (int b = 0; b < 8; ++b)
            #pragma unroll
            for (int c = 0; c < 4; ++c) accE[b][c] = 0.f;
        #pragma unroll
        for (int b = 0; b < 9; ++b)
            #pragma unroll
            for (int c = 0; c < 4; ++c) accB[b][c] = 0.f;

        float4 vc0 = __ldg((const float4*)pA[0][0]);
        float4 vc1 = __ldg((const float4*)pA[0][1]);
        #pragma unroll
        for (int s = 0; s < 12; ++s) {
            float4 vn0, vn1;
            if (s < 11) {
                const int sp = s + 1;
                vn0 = __ldg((const float4*)(pA[sp >> 2][0] + (sp & 3) * 64));
                vn1 = __ldg((const float4*)(pA[sp >> 2][1] + (sp & 3) * 64));
            }
            // fp16 A fragment: a0 = row g_ (k lo-pair), a1 = row g_+8, a2/a3 = hi-pair
            const uint32_t a0 = H2(vc0.x, vc0.y), a1 = H2(vc1.x, vc1.y);
            const uint32_t a2 = H2(vc0.z, vc0.w), a3 = H2(vc1.z, vc1.w);
            const int ko = s * 16 + 4 * t4;
            #pragma unroll
            for (int nt = 0; nt < 9; ++nt) {
                uint2 w = *(const uint2*)&swb[(nt * 8 + g_) * 208 + ko];
                mma_f16(accB[nt], a0, a1, a2, a3, w.x, w.y);
            }
            if (s < 4) {
                #pragma unroll
                for (int nt = 0; nt < 8; ++nt) {
                    uint2 w = *(const uint2*)&sw1[(nt * 8 + g_) * 80 + ko];
                    mma_f16(accE[nt], a0, a1, a2, a3, w.x, w.y);
                }
            }
            if (s < 11) { vc0 = vn0; vc1 = vn1; }
        }

        // ---------------- epilogue (registers only; actual-col float4 groups) ----------------
        #pragma unroll
        for (int hf = 0; hf < 2; ++hf) {
            const int h2  = hf * 2;
            const int row = hf * 8 + g_;

            float p[16], s1 = 0.f, s2 = 0.f;
            #pragma unroll
            for (int J = 0; J < 4; ++J) {
                float4 bm4 = *(const float4*)&sbm[J * 16 + t4 * 4];
                float pre[4] = { accB[2 * J][h2]     + bm4.x,
                                 accB[2 * J][h2 + 1] + bm4.y,
                                 accB[2 * J + 1][h2]     + bm4.z,
                                 accB[2 * J + 1][h2 + 1] + bm4.w };
                #pragma unroll
                for (int c = 0; c < 4; ++c) {
                    float th = 1.f - __fdividef(2.f, __expf(2.f * pre[c]) + 1.f);
                    p[J * 4 + c] = th;
                    s1 += th; s2 += th * th;
                }
            }
            s1 += __shfl_xor_sync(0xffffffffu, s1, 1);
            s1 += __shfl_xor_sync(0xffffffffu, s1, 2);
            s2 += __shfl_xor_sync(0xffffffffu, s2, 1);
            s2 += __shfl_xor_sync(0xffffffffu, s2, 2);
            float ap = accB[8][h2] + bma;
            ap = __shfl_sync(0xffffffffu, ap, lane & ~3);
            const float alpha = __fdividef(1.f, 1.f + __expf(-ap));
            const float mean  = s1 * (1.f / 64.f);
            const float var   = s2 * (1.f / 64.f) - mean * mean;
            const float rstd  = rsqrtf(var + LN_EPS) * alpha;

            float y[16], u1 = 0.f, u2 = 0.f;
            #pragma unroll
            for (int J = 0; J < 4; ++J) {
                float4 bi4 = *(const float4*)&sbi[J * 16 + t4 * 4];
                float y0 = accE[2 * J][h2]     + bi4.x + (p[J * 4 + 0] - mean) * rstd;
                float y1 = accE[2 * J][h2 + 1] + bi4.y + (p[J * 4 + 1] - mean) * rstd;
                float y2 = accE[2 * J + 1][h2]     + bi4.z + (p[J * 4 + 2] - mean) * rstd;
                float y3 = accE[2 * J + 1][h2 + 1] + bi4.w + (p[J * 4 + 3] - mean) * rstd;
                y[J * 4 + 0] = y0; y[J * 4 + 1] = y1; y[J * 4 + 2] = y2; y[J * 4 + 3] = y3;
                u1 += y0 + y1 + y2 + y3;
                u2 += y0 * y0 + y1 * y1 + y2 * y2 + y3 * y3;
            }
            u1 += __shfl_xor_sync(0xffffffffu, u1, 1);
            u1 += __shfl_xor_sync(0xffffffffu, u1, 2);
            u2 += __shfl_xor_sync(0xffffffffu, u2, 1);
            u2 += __shfl_xor_sync(0xffffffffu, u2, 2);
            const float m2  = u1 * (1.f / 64.f);
            const float v2  = u2 * (1.f / 64.f) - m2 * m2;
            const float rs2 = rsqrtf(v2 + LN_EPS);

            if (row < rem) {
                float* op = out + (size_t)(tb + row) * 64;
                #pragma unroll
                for (int J = 0; J < 4; ++J) {
                    float4 o;
                    o.x = (y[J * 4 + 0] - m2) * rs2;
                    o.y = (y[J * 4 + 1] - m2) * rs2;
                    o.z = (y[J * 4 + 2] - m2) * rs2;
                    o.w = (y[J * 4 + 3] - m2) * rs2;
                    *(float4*)(op + J * 16 + t4 * 4) = o;
                }
            }
        }
    }
}

extern "C" void kernel_launch(void* const* d_in, const int* in_sizes, int n_in,
                              void* d_out, int out_size)
{
    const float* node_fts = (const float*)d_in[0];
    const float* edge_fts = (const float*)d_in[1];
    const void*  edges    = d_in[2];
    const float* W_init   = (const float*)d_in[3];
    const float* b_init   = (const float*)d_in[4];
    const float* W_mlp    = (const float*)d_in[5];
    const float* b_mlp    = (const float*)d_in[6];
    const float* W_alpha  = (const float*)d_in[7];
    const float* b_alpha  = (const float*)d_in[8];
    float*       out      = (float*)d_out;

    const int n_edges = in_sizes[1] / 64;
    const int ntiles  = (n_edges + 15) / 16;

    int nsm = 148;
    cudaDeviceGetAttribute(&nsm, cudaDevAttrMultiProcessorCount, 0);
    int need = (ntiles + 7) / 8;
    int maxg = 2 * nsm;
    int grid = need < maxg ? need : maxg;

    cudaFuncSetAttribute(edge_update_v9,
                         cudaFuncAttributeMaxDynamicSharedMemorySize, SMEM_BYTES);
    prep_all<<<74, 256>>>(W_init, b_init, W_mlp, b_mlp, W_alpha, b_alpha,
                          (const long long*)edges);
    edge_update_v9<<<grid, NT, SMEM_BYTES>>>(node_fts, edge_fts, edges, out, n_edges);
}